// round 11
// baseline (speedup 1.0000x reference)
#include <cuda_runtime.h>
#include <stdint.h>

#define N_GRAPHS 1000
#define EPS 1e-5f
#define MAIN_THREADS 1024
#define MAIN_GRID 152   // 152 SMs; pinned L2 window < 126MB L2
#define SROWS 352       // rows staged in dynamic smem (352*512B = 176KB), 11 iters/group

__device__ int g_start[N_GRAPHS + 1];
__device__ unsigned int g_ticket;   // dynamic graph scheduler

// ---- L2 residency-hinted 128-bit loads via cache-policy descriptor --------
__device__ __forceinline__ unsigned long long mkpol_evict_last() {
    unsigned long long p;
    asm("createpolicy.fractional.L2::evict_last.b64 %0, 1.0;" : "=l"(p));
    return p;
}
__device__ __forceinline__ unsigned long long mkpol_evict_first() {
    unsigned long long p;
    asm("createpolicy.fractional.L2::evict_first.b64 %0, 1.0;" : "=l"(p));
    return p;
}
__device__ __forceinline__ float4 ldg_pol(const float4* p, unsigned long long pol) {
    float4 v;
    asm("ld.global.nc.L2::cache_hint.v4.f32 {%0,%1,%2,%3}, [%4], %5;"
        : "=f"(v.x), "=f"(v.y), "=f"(v.z), "=f"(v.w) : "l"(p), "l"(pol));
    return v;
}

// ---------------------------------------------------------------------------
// Kernel 1: segment boundaries (int4 vectorized) + ticket reset.
// ---------------------------------------------------------------------------
__global__ void find_starts_kernel(const int* __restrict__ batch, int n) {
    int i4 = blockIdx.x * blockDim.x + threadIdx.x;
    if (i4 == 0) g_ticket = 0;                 // reset scheduler every launch
    int base = i4 * 4;
    if (base >= n) return;

    int v[4];
    if (base + 3 < n) {
        int4 t = ((const int4*)batch)[i4];
        v[0] = t.x; v[1] = t.y; v[2] = t.z; v[3] = t.w;
    } else {
        for (int j = 0; j < 4; ++j) v[j] = (base + j < n) ? batch[base + j] : v[j > 0 ? j - 1 : 0];
    }
    int pb = (base == 0) ? -1 : min(max(batch[base - 1], 0), N_GRAPHS - 1);
    for (int j = 0; j < 4; ++j) {
        int idx = base + j;
        if (idx >= n) break;
        int b = min(max(v[j], 0), N_GRAPHS - 1);
        for (int g = pb + 1; g <= b; ++g) g_start[g] = idx;
        if (idx == n - 1) {
            for (int g = b + 1; g <= N_GRAPHS; ++g) g_start[g] = n;
        }
        pb = b;
    }
}

// ---------------------------------------------------------------------------
// Kernel 2: fused GraphNorm. Sequential per graph, dynamic tickets, L2 policy
// hints, SMEM staging of the first SROWS rows — with branch-free split loops
// so the staged path doesn't throttle MLP (R10 lesson).
//   lane = tid&31 -> channel quad; grp = tid>>5 -> row group (32 groups)
//   One-pass variance: var = E_w[x^2] + mean^2 * ms * (ms - 2)
//   out = A[c]*x + B[c],  A = weight*rsqrt(var+eps), B = bias - mean*ms*A
// ---------------------------------------------------------------------------
__global__ __launch_bounds__(MAIN_THREADS, 1)
void graphnorm_kernel(const float4* __restrict__ x,
                      const float* __restrict__ nw,
                      const float* __restrict__ weight,
                      const float* __restrict__ bias,
                      const float* __restrict__ msc,
                      float4* __restrict__ out) {
    __shared__ float s_sum [32][132];
    __shared__ float s_sum2[32][132];
    __shared__ float s_wp[32];
    __shared__ float s_A[128];
    __shared__ float s_B[128];
    __shared__ int   s_g;
    extern __shared__ float4 s_x[];   // [SROWS][32] staged x rows (176KB)

    const int tid  = threadIdx.x;
    const int lane = tid & 31;
    const int grp  = tid >> 5;

    const unsigned long long pol_last  = mkpol_evict_last();
    const unsigned long long pol_first = mkpol_evict_first();

    while (true) {
        if (tid == 0) s_g = (int)atomicAdd(&g_ticket, 1u);
        __syncthreads();
        const int g = s_g;
        if (g >= N_GRAPHS) break;

        const int start = g_start[g];
        const int end   = g_start[g + 1];
        const int len   = end - start;
        const int staged = min(len, SROWS);    // boundary is multiple of 32 when full

        float4 wx  = make_float4(0.f, 0.f, 0.f, 0.f);
        float4 wx2 = make_float4(0.f, 0.f, 0.f, 0.f);
        float  wa  = 0.f;

        // ---- Pass 1a: staged rows (LDG pinned + STS), branch-free ----
        #pragma unroll 4
        for (int rel = grp; rel < staged; rel += 32) {
            const int row = start + rel;
            float  w = __ldg(&nw[row]);
            float4 v = ldg_pol(&x[(size_t)row * 32 + lane], pol_last);
            s_x[rel * 32 + lane] = v;
            wa += w;
            wx.x += w * v.x;  wx.y += w * v.y;
            wx.z += w * v.z;  wx.w += w * v.w;
            wx2.x += w * v.x * v.x;  wx2.y += w * v.y * v.y;
            wx2.z += w * v.z * v.z;  wx2.w += w * v.w * v.w;
        }
        // ---- Pass 1b: tail rows (LDG pinned only) ----
        #pragma unroll 4
        for (int rel = SROWS + grp; rel < len; rel += 32) {
            const int row = start + rel;
            float  w = __ldg(&nw[row]);
            float4 v = ldg_pol(&x[(size_t)row * 32 + lane], pol_last);
            wa += w;
            wx.x += w * v.x;  wx.y += w * v.y;
            wx.z += w * v.z;  wx.w += w * v.w;
            wx2.x += w * v.x * v.x;  wx2.y += w * v.y * v.y;
            wx2.z += w * v.z * v.z;  wx2.w += w * v.w * v.w;
        }
        *(float4*)&s_sum [grp][4 * lane] = wx;
        *(float4*)&s_sum2[grp][4 * lane] = wx2;
        if (lane == 0) s_wp[grp] = wa;
        __syncthreads();

        // ---- Single-stage reduction + coefficients (threads 0..127) ----
        if (tid < 128) {                          // thread t owns channel t
            float swx = 0.f, swx2 = 0.f, sw = 0.f;
            #pragma unroll
            for (int g2 = 0; g2 < 32; ++g2) {
                swx  += s_sum [g2][tid];
                swx2 += s_sum2[g2][tid];
                sw   += s_wp[g2];
            }
            float inv_w = 1.0f / fmaxf(sw, 1e-12f);
            float m  = swx  * inv_w;
            float m2 = swx2 * inv_w;
            float ms = __ldg(&msc[tid]);
            float wt = __ldg(&weight[tid]);
            float bs = __ldg(&bias[tid]);
            float var = m2 + m * m * ms * (ms - 2.f);
            float a = wt * rsqrtf(var + EPS);
            s_A[tid] = a;
            s_B[tid] = bs - m * ms * a;
        }
        __syncthreads();

        const float4 A = *(const float4*)&s_A[4 * lane];
        const float4 B = *(const float4*)&s_B[4 * lane];

        // ---- Pass 2a: staged rows from smem (no global reads) ----
        #pragma unroll 4
        for (int rel = grp; rel < staged; rel += 32) {
            const int row = start + rel;
            float4 v = s_x[rel * 32 + lane];
            float4 o;
            o.x = fmaf(A.x, v.x, B.x);
            o.y = fmaf(A.y, v.y, B.y);
            o.z = fmaf(A.z, v.z, B.z);
            o.w = fmaf(A.w, v.w, B.w);
            __stcs(&out[(size_t)row * 32 + lane], o);
        }
        // ---- Pass 2b: tail rows from L2 (evict_first) ----
        #pragma unroll 4
        for (int rel = SROWS + grp; rel < len; rel += 32) {
            const int row = start + rel;
            float4 v = ldg_pol(&x[(size_t)row * 32 + lane], pol_first);
            float4 o;
            o.x = fmaf(A.x, v.x, B.x);
            o.y = fmaf(A.y, v.y, B.y);
            o.z = fmaf(A.z, v.z, B.z);
            o.w = fmaf(A.w, v.w, B.w);
            __stcs(&out[(size_t)row * 32 + lane], o);
        }
        __syncthreads();   // smem reuse safety for next iteration
    }
}

// ---------------------------------------------------------------------------
// Launch
// ---------------------------------------------------------------------------
extern "C" void kernel_launch(void* const* d_in, const int* in_sizes, int n_in,
                              void* d_out, int out_size) {
    const float* x      = (const float*)d_in[0];
    const int*   batch  = (const int*)d_in[1];     // int32 (JAX x64 disabled)
    const float* nw     = (const float*)d_in[2];
    const float* weight = (const float*)d_in[3];
    const float* bias   = (const float*)d_in[4];
    const float* msc    = (const float*)d_in[5];
    float* out = (float*)d_out;

    const int n = in_sizes[1];
    const int dyn_smem = SROWS * 32 * sizeof(float4);   // 176 KB

    cudaFuncSetAttribute(graphnorm_kernel,
                         cudaFuncAttributeMaxDynamicSharedMemorySize, dyn_smem);

    const int n4 = (n + 3) / 4;
    find_starts_kernel<<<(n4 + 255) / 256, 256>>>(batch, n);
    graphnorm_kernel<<<MAIN_GRID, MAIN_THREADS, dyn_smem>>>(
        (const float4*)x, nw, weight, bias, msc, (float4*)out);
}

// round 12
// speedup vs baseline: 1.0654x; 1.0654x over previous
#include <cuda_runtime.h>
#include <stdint.h>

#define N_GRAPHS 1000
#define EPS 1e-5f
#define MAIN_THREADS 1024
#define MAIN_GRID 152   // 152 SMs; pinned L2 window 152*512KB=78MB < 126MB L2

__device__ int g_start[N_GRAPHS + 1];
__device__ unsigned int g_ticket;   // dynamic graph scheduler

// ---- L2 residency-hinted 128-bit loads via cache-policy descriptor --------
__device__ __forceinline__ unsigned long long mkpol_evict_last() {
    unsigned long long p;
    asm("createpolicy.fractional.L2::evict_last.b64 %0, 1.0;" : "=l"(p));
    return p;
}
__device__ __forceinline__ unsigned long long mkpol_evict_first() {
    unsigned long long p;
    asm("createpolicy.fractional.L2::evict_first.b64 %0, 1.0;" : "=l"(p));
    return p;
}
__device__ __forceinline__ float4 ldg_pol(const float4* p, unsigned long long pol) {
    float4 v;
    asm("ld.global.nc.L2::cache_hint.v4.f32 {%0,%1,%2,%3}, [%4], %5;"
        : "=f"(v.x), "=f"(v.y), "=f"(v.z), "=f"(v.w) : "l"(p), "l"(pol));
    return v;
}

// ---------------------------------------------------------------------------
// Kernel 1: segment boundaries (int4 vectorized) + ticket reset.
// No early returns (all threads reach the block-level PDL trigger).
// ---------------------------------------------------------------------------
__global__ void find_starts_kernel(const int* __restrict__ batch, int n) {
    int i4 = blockIdx.x * blockDim.x + threadIdx.x;
    if (i4 == 0) g_ticket = 0;                 // reset scheduler every launch
    int base = i4 * 4;
    if (base < n) {
        int v[4];
        if (base + 3 < n) {
            int4 t = ((const int4*)batch)[i4];
            v[0] = t.x; v[1] = t.y; v[2] = t.z; v[3] = t.w;
        } else {
            for (int j = 0; j < 4; ++j)
                v[j] = (base + j < n) ? batch[base + j] : v[j > 0 ? j - 1 : 0];
        }
        int pb = (base == 0) ? -1 : min(max(batch[base - 1], 0), N_GRAPHS - 1);
        for (int j = 0; j < 4; ++j) {
            int idx = base + j;
            if (idx >= n) break;
            int b = min(max(v[j], 0), N_GRAPHS - 1);
            for (int g = pb + 1; g <= b; ++g) g_start[g] = idx;
            if (idx == n - 1) {
                for (int g = b + 1; g <= N_GRAPHS; ++g) g_start[g] = n;
            }
            pb = b;
        }
    }
    __syncthreads();
    if (threadIdx.x == 0) {
        __threadfence();                              // publish g_start/g_ticket
        cudaTriggerProgrammaticLaunchCompletion();    // release dependent kernel
    }
}

// ---------------------------------------------------------------------------
// Kernel 2: fused GraphNorm (R9 memory path), PDL-gated start, parallel reduce.
//   lane = tid&31 -> channel quad; grp = tid>>5 -> row group (32 groups)
//   One-pass variance: var = E_w[x^2] + mean^2 * ms * (ms - 2)
//   out = A[c]*x + B[c],  A = weight*rsqrt(var+eps), B = bias - mean*ms*A
// ---------------------------------------------------------------------------
__global__ __launch_bounds__(MAIN_THREADS, 1)
void graphnorm_kernel(const float4* __restrict__ x,
                      const float* __restrict__ nw,
                      const float* __restrict__ weight,
                      const float* __restrict__ bias,
                      const float* __restrict__ msc,
                      float4* __restrict__ out) {
    __shared__ float s_sum [32][132];
    __shared__ float s_sum2[32][132];
    __shared__ float s_red1[8][128];
    __shared__ float s_red2[8][128];
    __shared__ float s_wp[32];
    __shared__ float s_wj[8];
    __shared__ float s_A[128];
    __shared__ float s_B[128];
    __shared__ int   s_g;

    const int tid  = threadIdx.x;
    const int lane = tid & 31;
    const int grp  = tid >> 5;

    cudaGridDependencySynchronize();   // wait for find_starts results (PDL)

    const unsigned long long pol_last  = mkpol_evict_last();
    const unsigned long long pol_first = mkpol_evict_first();

    while (true) {
        if (tid == 0) s_g = (int)atomicAdd(&g_ticket, 1u);
        __syncthreads();
        const int g = s_g;
        if (g >= N_GRAPHS) break;

        const int start = g_start[g];
        const int end   = g_start[g + 1];

        // ---- Pass 1: weighted sums (DRAM read; pin lines in L2) ----
        float4 wx  = make_float4(0.f, 0.f, 0.f, 0.f);
        float4 wx2 = make_float4(0.f, 0.f, 0.f, 0.f);
        float  wa  = 0.f;
        #pragma unroll 4
        for (int r = start + grp; r < end; r += 32) {
            float  w = __ldg(&nw[r]);
            float4 v = ldg_pol(&x[(size_t)r * 32 + lane], pol_last);  // pin for reuse
            wa += w;
            wx.x += w * v.x;  wx.y += w * v.y;
            wx.z += w * v.z;  wx.w += w * v.w;
            wx2.x += w * v.x * v.x;  wx2.y += w * v.y * v.y;
            wx2.z += w * v.z * v.z;  wx2.w += w * v.w * v.w;
        }
        *(float4*)&s_sum [grp][4 * lane] = wx;
        *(float4*)&s_sum2[grp][4 * lane] = wx2;
        if (lane == 0) s_wp[grp] = wa;
        __syncthreads();

        // ---- Reduce stage A: all 1024 threads, each sums 4 group-partials ----
        {
            const int ch = tid & 127;          // channel
            const int j  = tid >> 7;           // 0..7: group quad
            const int g0 = j * 4;
            float a1 = s_sum [g0][ch] + s_sum [g0+1][ch]
                     + s_sum [g0+2][ch] + s_sum [g0+3][ch];
            float a2 = s_sum2[g0][ch] + s_sum2[g0+1][ch]
                     + s_sum2[g0+2][ch] + s_sum2[g0+3][ch];
            s_red1[j][ch] = a1;
            s_red2[j][ch] = a2;
            if (tid < 8)
                s_wj[tid] = s_wp[tid*4] + s_wp[tid*4+1] + s_wp[tid*4+2] + s_wp[tid*4+3];
        }
        __syncthreads();

        // ---- Reduce stage B + coefficients: 128 threads, channel each ----
        if (tid < 128) {
            float swx = 0.f, swx2 = 0.f, sw = 0.f;
            #pragma unroll
            for (int j = 0; j < 8; ++j) {
                swx  += s_red1[j][tid];
                swx2 += s_red2[j][tid];
                sw   += s_wj[j];
            }
            float inv_w = 1.0f / fmaxf(sw, 1e-12f);
            float m  = swx  * inv_w;
            float m2 = swx2 * inv_w;
            float ms = __ldg(&msc[tid]);
            float wt = __ldg(&weight[tid]);
            float bs = __ldg(&bias[tid]);
            float var = m2 + m * m * ms * (ms - 2.f);
            float a = wt * rsqrtf(var + EPS);
            s_A[tid] = a;
            s_B[tid] = bs - m * ms * a;
        }
        __syncthreads();

        const float4 A = *(const float4*)&s_A[4 * lane];
        const float4 B = *(const float4*)&s_B[4 * lane];

        // ---- Pass 2: normalize + write (L2 hits; release lines) ----
        #pragma unroll 4
        for (int r = start + grp; r < end; r += 32) {
            float4 v = ldg_pol(&x[(size_t)r * 32 + lane], pol_first); // last use
            float4 o;
            o.x = fmaf(A.x, v.x, B.x);
            o.y = fmaf(A.y, v.y, B.y);
            o.z = fmaf(A.z, v.z, B.z);
            o.w = fmaf(A.w, v.w, B.w);
            __stcs(&out[(size_t)r * 32 + lane], o);         // streaming store
        }
        __syncthreads();   // smem/s_g reuse safety for next iteration
    }
}

// ---------------------------------------------------------------------------
// Launch: find_starts, then graphnorm with PDL so its launch overlaps.
// ---------------------------------------------------------------------------
extern "C" void kernel_launch(void* const* d_in, const int* in_sizes, int n_in,
                              void* d_out, int out_size) {
    const float* x      = (const float*)d_in[0];
    const int*   batch  = (const int*)d_in[1];     // int32 (JAX x64 disabled)
    const float* nw     = (const float*)d_in[2];
    const float* weight = (const float*)d_in[3];
    const float* bias   = (const float*)d_in[4];
    const float* msc    = (const float*)d_in[5];
    float* out = (float*)d_out;

    const int n = in_sizes[1];

    const int n4 = (n + 3) / 4;
    find_starts_kernel<<<(n4 + 255) / 256, 256>>>(batch, n);

    cudaLaunchConfig_t cfg = {};
    cfg.gridDim  = dim3(MAIN_GRID, 1, 1);
    cfg.blockDim = dim3(MAIN_THREADS, 1, 1);
    cfg.dynamicSmemBytes = 0;
    cfg.stream = 0;
    cudaLaunchAttribute attrs[1];
    attrs[0].id = cudaLaunchAttributeProgrammaticStreamSerialization;
    attrs[0].val.programmaticStreamSerializationAllowed = 1;
    cfg.attrs = attrs;
    cfg.numAttrs = 1;
    cudaLaunchKernelEx(&cfg, graphnorm_kernel,
                       (const float4*)x, nw, weight, bias, msc, (float4*)out);
}

// round 13
// speedup vs baseline: 1.0717x; 1.0059x over previous
#include <cuda_runtime.h>
#include <stdint.h>

#define N_GRAPHS 1000
#define EPS 1e-5f
#define MAIN_THREADS 1024
#define MAIN_GRID 152   // 152 SMs; pinned L2 window 152*512KB=78MB < 126MB L2

__device__ int g_start[N_GRAPHS + 1];
__device__ unsigned int g_ticket;   // dynamic graph scheduler

// ---- L2 residency-hinted 128-bit loads via cache-policy descriptor --------
__device__ __forceinline__ unsigned long long mkpol_evict_last() {
    unsigned long long p;
    asm("createpolicy.fractional.L2::evict_last.b64 %0, 1.0;" : "=l"(p));
    return p;
}
__device__ __forceinline__ unsigned long long mkpol_evict_first() {
    unsigned long long p;
    asm("createpolicy.fractional.L2::evict_first.b64 %0, 1.0;" : "=l"(p));
    return p;
}
__device__ __forceinline__ float4 ldg_pol(const float4* p, unsigned long long pol) {
    float4 v;
    asm("ld.global.nc.L2::cache_hint.v4.f32 {%0,%1,%2,%3}, [%4], %5;"
        : "=f"(v.x), "=f"(v.y), "=f"(v.z), "=f"(v.w) : "l"(p), "l"(pol));
    return v;
}

// ---------------------------------------------------------------------------
// Kernel 1: segment boundaries. 16 elements per thread (4x int4) to shrink
// the grid (~980 blocks) and dispatch cost. Ticket reset + PDL trigger.
// ---------------------------------------------------------------------------
#define FS_ELEMS 16
__global__ void find_starts_kernel(const int* __restrict__ batch, int n) {
    int t = blockIdx.x * blockDim.x + threadIdx.x;
    if (t == 0) g_ticket = 0;                  // reset scheduler every launch
    int base = t * FS_ELEMS;
    if (base < n) {
        int pb = (base == 0) ? -1 : min(max(__ldg(&batch[base - 1]), 0), N_GRAPHS - 1);
        #pragma unroll
        for (int q = 0; q < FS_ELEMS / 4; ++q) {
            int b0 = base + q * 4;
            if (b0 >= n) break;
            int v[4];
            if (b0 + 3 < n) {
                int4 tt = __ldg((const int4*)(batch + b0));
                v[0] = tt.x; v[1] = tt.y; v[2] = tt.z; v[3] = tt.w;
            } else {
                for (int j = 0; j < 4; ++j)
                    v[j] = (b0 + j < n) ? __ldg(&batch[b0 + j]) : v[j > 0 ? j - 1 : 0];
            }
            for (int j = 0; j < 4; ++j) {
                int idx = b0 + j;
                if (idx >= n) break;
                int b = min(max(v[j], 0), N_GRAPHS - 1);
                for (int g = pb + 1; g <= b; ++g) g_start[g] = idx;
                if (idx == n - 1) {
                    for (int g = b + 1; g <= N_GRAPHS; ++g) g_start[g] = n;
                }
                pb = b;
            }
        }
    }
    __syncthreads();
    if (threadIdx.x == 0) {
        __threadfence();
        cudaTriggerProgrammaticLaunchCompletion();
    }
}

// ---------------------------------------------------------------------------
// Kernel 2: fused GraphNorm. R12 memory path + REVERSE-ORDER pass 2 so the
// most-recently-filled L2 lines are re-read first (minimal reuse distance).
//   lane = tid&31 -> channel quad; grp = tid>>5 -> row group (32 groups)
//   One-pass variance: var = E_w[x^2] + mean^2 * ms * (ms - 2)
//   out = A[c]*x + B[c],  A = weight*rsqrt(var+eps), B = bias - mean*ms*A
// ---------------------------------------------------------------------------
__global__ __launch_bounds__(MAIN_THREADS, 1)
void graphnorm_kernel(const float4* __restrict__ x,
                      const float* __restrict__ nw,
                      const float* __restrict__ weight,
                      const float* __restrict__ bias,
                      const float* __restrict__ msc,
                      float4* __restrict__ out) {
    __shared__ float s_sum [32][132];
    __shared__ float s_sum2[32][132];
    __shared__ float s_red1[8][128];
    __shared__ float s_red2[8][128];
    __shared__ float s_wp[32];
    __shared__ float s_wj[8];
    __shared__ float s_A[128];
    __shared__ float s_B[128];
    __shared__ int   s_g;

    const int tid  = threadIdx.x;
    const int lane = tid & 31;
    const int grp  = tid >> 5;

    cudaGridDependencySynchronize();   // wait for find_starts results (PDL)

    const unsigned long long pol_last  = mkpol_evict_last();
    const unsigned long long pol_first = mkpol_evict_first();

    while (true) {
        if (tid == 0) s_g = (int)atomicAdd(&g_ticket, 1u);
        __syncthreads();
        const int g = s_g;
        if (g >= N_GRAPHS) break;

        const int start = g_start[g];
        const int end   = g_start[g + 1];
        const int len   = end - start;

        // ---- Pass 1: weighted sums, forward order (pin lines in L2) ----
        float4 wx  = make_float4(0.f, 0.f, 0.f, 0.f);
        float4 wx2 = make_float4(0.f, 0.f, 0.f, 0.f);
        float  wa  = 0.f;
        #pragma unroll 4
        for (int r = start + grp; r < end; r += 32) {
            float  w = __ldg(&nw[r]);
            float4 v = ldg_pol(&x[(size_t)r * 32 + lane], pol_last);
            wa += w;
            wx.x += w * v.x;  wx.y += w * v.y;
            wx.z += w * v.z;  wx.w += w * v.w;
            wx2.x += w * v.x * v.x;  wx2.y += w * v.y * v.y;
            wx2.z += w * v.z * v.z;  wx2.w += w * v.w * v.w;
        }
        *(float4*)&s_sum [grp][4 * lane] = wx;
        *(float4*)&s_sum2[grp][4 * lane] = wx2;
        if (lane == 0) s_wp[grp] = wa;
        __syncthreads();

        // ---- Reduce stage A: all 1024 threads, each sums 4 group-partials ----
        {
            const int ch = tid & 127;
            const int j  = tid >> 7;
            const int g0 = j * 4;
            s_red1[j][ch] = s_sum [g0][ch] + s_sum [g0+1][ch]
                          + s_sum [g0+2][ch] + s_sum [g0+3][ch];
            s_red2[j][ch] = s_sum2[g0][ch] + s_sum2[g0+1][ch]
                          + s_sum2[g0+2][ch] + s_sum2[g0+3][ch];
            if (tid < 8)
                s_wj[tid] = s_wp[tid*4] + s_wp[tid*4+1] + s_wp[tid*4+2] + s_wp[tid*4+3];
        }
        __syncthreads();

        // ---- Reduce stage B + coefficients: 128 threads, one channel each ----
        if (tid < 128) {
            float swx = 0.f, swx2 = 0.f, sw = 0.f;
            #pragma unroll
            for (int j = 0; j < 8; ++j) {
                swx  += s_red1[j][tid];
                swx2 += s_red2[j][tid];
                sw   += s_wj[j];
            }
            float inv_w = 1.0f / fmaxf(sw, 1e-12f);
            float m  = swx  * inv_w;
            float m2 = swx2 * inv_w;
            float ms = __ldg(&msc[tid]);
            float wt = __ldg(&weight[tid]);
            float bs = __ldg(&bias[tid]);
            float var = m2 + m * m * ms * (ms - 2.f);
            float a = wt * rsqrtf(var + EPS);
            s_A[tid] = a;
            s_B[tid] = bs - m * ms * a;
        }
        __syncthreads();

        const float4 A = *(const float4*)&s_A[4 * lane];
        const float4 B = *(const float4*)&s_B[4 * lane];

        // ---- Pass 2: REVERSE order (LIFO re-read minimizes L2 misses) ----
        if (grp < len) {
            const int rlo = start + grp;                       // lowest row for this grp
            const int rhi = rlo + ((len - 1 - grp) / 32) * 32; // highest row for this grp
            #pragma unroll 4
            for (int r = rhi; r >= rlo; r -= 32) {
                float4 v = ldg_pol(&x[(size_t)r * 32 + lane], pol_first);
                float4 o;
                o.x = fmaf(A.x, v.x, B.x);
                o.y = fmaf(A.y, v.y, B.y);
                o.z = fmaf(A.z, v.z, B.z);
                o.w = fmaf(A.w, v.w, B.w);
                __stcs(&out[(size_t)r * 32 + lane], o);
            }
        }
        __syncthreads();   // smem/s_g reuse safety for next iteration
    }
}

// ---------------------------------------------------------------------------
// Launch: find_starts, then graphnorm with PDL.
// ---------------------------------------------------------------------------
extern "C" void kernel_launch(void* const* d_in, const int* in_sizes, int n_in,
                              void* d_out, int out_size) {
    const float* x      = (const float*)d_in[0];
    const int*   batch  = (const int*)d_in[1];     // int32 (JAX x64 disabled)
    const float* nw     = (const float*)d_in[2];
    const float* weight = (const float*)d_in[3];
    const float* bias   = (const float*)d_in[4];
    const float* msc    = (const float*)d_in[5];
    float* out = (float*)d_out;

    const int n = in_sizes[1];

    const int nt = (n + FS_ELEMS - 1) / FS_ELEMS;
    find_starts_kernel<<<(nt + 255) / 256, 256>>>(batch, n);

    cudaLaunchConfig_t cfg = {};
    cfg.gridDim  = dim3(MAIN_GRID, 1, 1);
    cfg.blockDim = dim3(MAIN_THREADS, 1, 1);
    cfg.dynamicSmemBytes = 0;
    cfg.stream = 0;
    cudaLaunchAttribute attrs[1];
    attrs[0].id = cudaLaunchAttributeProgrammaticStreamSerialization;
    attrs[0].val.programmaticStreamSerializationAllowed = 1;
    cfg.attrs = attrs;
    cfg.numAttrs = 1;
    cudaLaunchKernelEx(&cfg, graphnorm_kernel,
                       (const float4*)x, nw, weight, bias, msc, (float4*)out);
}

// round 14
// speedup vs baseline: 1.0726x; 1.0008x over previous
#include <cuda_runtime.h>
#include <stdint.h>

#define N_GRAPHS 1000
#define EPS 1e-5f
#define MAIN_THREADS 1024
#define MAIN_GRID 152   // = SM count; 1 block/SM guarantees co-residency (safe spin barrier)
#define FS_ELEMS 8      // batch elems per thread in the boundary prologue

__device__ int g_start[N_GRAPHS + 1];
__device__ unsigned int g_ticket;   // zero-init at module load; reset by epilogue
__device__ unsigned int g_arrive;
__device__ unsigned int g_done;

// ---- L2 residency-hinted 128-bit loads via cache-policy descriptor --------
__device__ __forceinline__ unsigned long long mkpol_evict_last() {
    unsigned long long p;
    asm("createpolicy.fractional.L2::evict_last.b64 %0, 1.0;" : "=l"(p));
    return p;
}
__device__ __forceinline__ unsigned long long mkpol_evict_first() {
    unsigned long long p;
    asm("createpolicy.fractional.L2::evict_first.b64 %0, 1.0;" : "=l"(p));
    return p;
}
__device__ __forceinline__ float4 ldg_pol(const float4* p, unsigned long long pol) {
    float4 v;
    asm("ld.global.nc.L2::cache_hint.v4.f32 {%0,%1,%2,%3}, [%4], %5;"
        : "=f"(v.x), "=f"(v.y), "=f"(v.z), "=f"(v.w) : "l"(p), "l"(pol));
    return v;
}
__device__ __forceinline__ unsigned int ld_volatile_u32(const unsigned int* p) {
    unsigned int v;
    asm volatile("ld.global.acquire.gpu.u32 %0, [%1];" : "=r"(v) : "l"(p));
    return v;
}

// ---------------------------------------------------------------------------
// Single persistent kernel:
//   Phase 0: cooperative segment-boundary computation + device-wide barrier.
//   Phase 1: per-graph GraphNorm with dynamic tickets (R13 memory path).
//   Epilogue: last block resets scheduler globals for the next replay.
// ---------------------------------------------------------------------------
__global__ __launch_bounds__(MAIN_THREADS, 1)
void graphnorm_fused_kernel(const float4* __restrict__ x,
                            const int*    __restrict__ batch,
                            const float*  __restrict__ nw,
                            const float*  __restrict__ weight,
                            const float*  __restrict__ bias,
                            const float*  __restrict__ msc,
                            float4* __restrict__ out,
                            int n) {
    __shared__ float s_sum [32][132];
    __shared__ float s_sum2[32][132];
    __shared__ float s_red1[8][128];
    __shared__ float s_red2[8][128];
    __shared__ float s_wp[32];
    __shared__ float s_wj[8];
    __shared__ float s_A[128];
    __shared__ float s_B[128];
    __shared__ int   s_g;

    const int tid  = threadIdx.x;
    const int lane = tid & 31;
    const int grp  = tid >> 5;

    // ================= Phase 0: segment boundaries =================
    {
        const int gtid = blockIdx.x * MAIN_THREADS + tid;
        const int base = gtid * FS_ELEMS;
        if (base < n) {
            int pb = (base == 0) ? -1
                                 : min(max(__ldg(&batch[base - 1]), 0), N_GRAPHS - 1);
            #pragma unroll
            for (int q = 0; q < FS_ELEMS / 4; ++q) {
                int b0 = base + q * 4;
                if (b0 >= n) break;
                int v[4];
                if (b0 + 3 < n) {
                    int4 tt = __ldg((const int4*)(batch + b0));
                    v[0] = tt.x; v[1] = tt.y; v[2] = tt.z; v[3] = tt.w;
                } else {
                    for (int j = 0; j < 4; ++j)
                        v[j] = (b0 + j < n) ? __ldg(&batch[b0 + j]) : v[j > 0 ? j - 1 : 0];
                }
                for (int j = 0; j < 4; ++j) {
                    int idx = b0 + j;
                    if (idx >= n) break;
                    int b = min(max(v[j], 0), N_GRAPHS - 1);
                    for (int gg = pb + 1; gg <= b; ++gg) g_start[gg] = idx;
                    if (idx == n - 1) {
                        for (int gg = b + 1; gg <= N_GRAPHS; ++gg) g_start[gg] = n;
                    }
                    pb = b;
                }
            }
        }
        __syncthreads();
        if (tid == 0) {
            __threadfence();                       // publish g_start
            atomicAdd(&g_arrive, 1u);
            while (ld_volatile_u32(&g_arrive) < MAIN_GRID) { /* spin */ }
        }
        __syncthreads();                           // whole block released
    }

    // ================= Phase 1: GraphNorm =================
    const unsigned long long pol_last  = mkpol_evict_last();
    const unsigned long long pol_first = mkpol_evict_first();

    while (true) {
        if (tid == 0) s_g = (int)atomicAdd(&g_ticket, 1u);
        __syncthreads();
        const int g = s_g;
        if (g >= N_GRAPHS) break;

        const int start = g_start[g];
        const int end   = g_start[g + 1];
        const int len   = end - start;

        // ---- Pass 1: weighted sums, forward order (pin lines in L2) ----
        float4 wx  = make_float4(0.f, 0.f, 0.f, 0.f);
        float4 wx2 = make_float4(0.f, 0.f, 0.f, 0.f);
        float  wa  = 0.f;
        #pragma unroll 4
        for (int r = start + grp; r < end; r += 32) {
            float  w = __ldg(&nw[r]);
            float4 v = ldg_pol(&x[(size_t)r * 32 + lane], pol_last);
            wa += w;
            wx.x += w * v.x;  wx.y += w * v.y;
            wx.z += w * v.z;  wx.w += w * v.w;
            wx2.x += w * v.x * v.x;  wx2.y += w * v.y * v.y;
            wx2.z += w * v.z * v.z;  wx2.w += w * v.w * v.w;
        }
        *(float4*)&s_sum [grp][4 * lane] = wx;
        *(float4*)&s_sum2[grp][4 * lane] = wx2;
        if (lane == 0) s_wp[grp] = wa;
        __syncthreads();

        // ---- Reduce stage A: 1024 threads, each sums 4 group-partials ----
        {
            const int ch = tid & 127;
            const int j  = tid >> 7;
            const int g0 = j * 4;
            s_red1[j][ch] = s_sum [g0][ch] + s_sum [g0+1][ch]
                          + s_sum [g0+2][ch] + s_sum [g0+3][ch];
            s_red2[j][ch] = s_sum2[g0][ch] + s_sum2[g0+1][ch]
                          + s_sum2[g0+2][ch] + s_sum2[g0+3][ch];
            if (tid < 8)
                s_wj[tid] = s_wp[tid*4] + s_wp[tid*4+1] + s_wp[tid*4+2] + s_wp[tid*4+3];
        }
        __syncthreads();

        // ---- Reduce stage B + coefficients: 128 threads ----
        if (tid < 128) {
            float swx = 0.f, swx2 = 0.f, sw = 0.f;
            #pragma unroll
            for (int j = 0; j < 8; ++j) {
                swx  += s_red1[j][tid];
                swx2 += s_red2[j][tid];
                sw   += s_wj[j];
            }
            float inv_w = 1.0f / fmaxf(sw, 1e-12f);
            float m  = swx  * inv_w;
            float m2 = swx2 * inv_w;
            float ms = __ldg(&msc[tid]);
            float wt = __ldg(&weight[tid]);
            float bs = __ldg(&bias[tid]);
            float var = m2 + m * m * ms * (ms - 2.f);
            float a = wt * rsqrtf(var + EPS);
            s_A[tid] = a;
            s_B[tid] = bs - m * ms * a;
        }
        __syncthreads();

        const float4 A = *(const float4*)&s_A[4 * lane];
        const float4 B = *(const float4*)&s_B[4 * lane];

        // ---- Pass 2: reverse order (most-recently-filled L2 lines first) ----
        if (grp < len) {
            const int rlo = start + grp;
            const int rhi = rlo + ((len - 1 - grp) / 32) * 32;
            #pragma unroll 4
            for (int r = rhi; r >= rlo; r -= 32) {
                float4 v = ldg_pol(&x[(size_t)r * 32 + lane], pol_first);
                float4 o;
                o.x = fmaf(A.x, v.x, B.x);
                o.y = fmaf(A.y, v.y, B.y);
                o.z = fmaf(A.z, v.z, B.z);
                o.w = fmaf(A.w, v.w, B.w);
                __stcs(&out[(size_t)r * 32 + lane], o);
            }
        }
        __syncthreads();
    }

    // ================= Epilogue: reset globals for next replay =================
    if (tid == 0) {
        __threadfence();
        unsigned int d = atomicAdd(&g_done, 1u);
        if (d == MAIN_GRID - 1) {                 // last block out resets everything
            g_ticket = 0;
            g_arrive = 0;
            g_done   = 0;
            __threadfence();
        }
    }
}

// ---------------------------------------------------------------------------
// Launch: single persistent kernel.
// ---------------------------------------------------------------------------
extern "C" void kernel_launch(void* const* d_in, const int* in_sizes, int n_in,
                              void* d_out, int out_size) {
    const float* x      = (const float*)d_in[0];
    const int*   batch  = (const int*)d_in[1];     // int32 (JAX x64 disabled)
    const float* nw     = (const float*)d_in[2];
    const float* weight = (const float*)d_in[3];
    const float* bias   = (const float*)d_in[4];
    const float* msc    = (const float*)d_in[5];
    float* out = (float*)d_out;

    const int n = in_sizes[1];

    graphnorm_fused_kernel<<<MAIN_GRID, MAIN_THREADS>>>(
        (const float4*)x, batch, nw, weight, bias, msc, (float4*)out, n);
}